// round 2
// baseline (speedup 1.0000x reference)
#include <cuda_runtime.h>

#define Hh 1024
#define Ww 1024
#define Bb 16
#define DIL 2
#define NTHREADS 256
#define NROWS (Bb * Hh)          // 16384 blocks, one per image row
#define NELEM ((long long)Bb * Hh * Ww)

__device__ float g_partial[NROWS];

__global__ __launch_bounds__(NTHREADS)
void consistency_main(const float* __restrict__ yt, const float* __restrict__ yp) {
    // Shared rows with 2-float halo on each side (shared idx = data idx + DIL).
    // Reads of the window [x-2, x+5] land at shared [x, x+7]: two aligned LDS.128.
    // Writes at shared offset DIL+x4 are only 8B-aligned -> stored as two float2.
    __shared__ alignas(16) float sU[Ww + 2 * DIL];
    __shared__ alignas(16) float sM[Ww + 2 * DIL];
    __shared__ alignas(16) float sD[Ww + 2 * DIL];
    __shared__ float warp_sums[NTHREADS / 32];

    const int row = blockIdx.x;          // 0..16383
    const int b   = row >> 10;
    const int y   = row & (Hh - 1);
    const int tid = threadIdx.x;
    const int x4  = tid * 4;

    const float* img = yp + (size_t)b * Hh * Ww;

    // Center row
    float4 c = *reinterpret_cast<const float4*>(img + (size_t)y * Ww + x4);
    *reinterpret_cast<float2*>(&sM[DIL + x4])     = make_float2(c.x, c.y);
    *reinterpret_cast<float2*>(&sM[DIL + x4 + 2]) = make_float2(c.z, c.w);

    // Row y-2 (zero pad outside image)
    float4 up = make_float4(0.f, 0.f, 0.f, 0.f);
    if (y >= DIL) up = *reinterpret_cast<const float4*>(img + (size_t)(y - DIL) * Ww + x4);
    *reinterpret_cast<float2*>(&sU[DIL + x4])     = make_float2(up.x, up.y);
    *reinterpret_cast<float2*>(&sU[DIL + x4 + 2]) = make_float2(up.z, up.w);

    // Row y+2 (zero pad outside image)
    float4 dn = make_float4(0.f, 0.f, 0.f, 0.f);
    if (y < Hh - DIL) dn = *reinterpret_cast<const float4*>(img + (size_t)(y + DIL) * Ww + x4);
    *reinterpret_cast<float2*>(&sD[DIL + x4])     = make_float2(dn.x, dn.y);
    *reinterpret_cast<float2*>(&sD[DIL + x4 + 2]) = make_float2(dn.z, dn.w);

    // Zero the left/right halos (image boundary zero-pad)
    if (tid < DIL) {
        sU[tid] = 0.f; sM[tid] = 0.f; sD[tid] = 0.f;
        sU[Ww + DIL + tid] = 0.f; sM[Ww + DIL + tid] = 0.f; sD[Ww + DIL + tid] = 0.f;
    }

    // y_true for this thread's 4 pixels (16B-aligned)
    float4 t4 = *reinterpret_cast<const float4*>(yt + (size_t)b * Hh * Ww + (size_t)y * Ww + x4);

    __syncthreads();

    // Pull the 8-wide windows (data x4-2 .. x4+5) as two aligned float4s each
    float u[8], m[8], d[8];
    *reinterpret_cast<float4*>(&u[0]) = *reinterpret_cast<const float4*>(&sU[x4]);
    *reinterpret_cast<float4*>(&u[4]) = *reinterpret_cast<const float4*>(&sU[x4 + 4]);
    *reinterpret_cast<float4*>(&m[0]) = *reinterpret_cast<const float4*>(&sM[x4]);
    *reinterpret_cast<float4*>(&m[4]) = *reinterpret_cast<const float4*>(&sM[x4 + 4]);
    *reinterpret_cast<float4*>(&d[0]) = *reinterpret_cast<const float4*>(&sD[x4]);
    *reinterpret_cast<float4*>(&d[4]) = *reinterpret_cast<const float4*>(&sD[x4 + 4]);

    const float tval[4] = { t4.x, t4.y, t4.z, t4.w };

    float lsum = 0.f;
#pragma unroll
    for (int j = 0; j < 4; ++j) {
        const float p = m[j + 2];           // center pixel
        const float t = tval[j];

        // BCE term: log_p = max(log p, -100); log_1p = max(log(1-p), -100)
        float lp = fmaxf(__logf(p),        -100.0f);
        float l1 = fmaxf(__logf(1.0f - p), -100.0f);
        float a  = -(t * lp + (1.0f - t) * l1);

        // Max |p - neighbor| over 8 dilated neighbors (zero pad already in windows)
        float uw;
        uw =             fabsf(p - u[j]);
        uw = fmaxf(uw,   fabsf(p - u[j + 2]));
        uw = fmaxf(uw,   fabsf(p - u[j + 4]));
        uw = fmaxf(uw,   fabsf(p - m[j]));
        uw = fmaxf(uw,   fabsf(p - m[j + 4]));
        uw = fmaxf(uw,   fabsf(p - d[j]));
        uw = fmaxf(uw,   fabsf(p - d[j + 2]));
        uw = fmaxf(uw,   fabsf(p - d[j + 4]));

        const float thred = (p >= 0.5f) ? p : 0.0f;
        lsum += fmaf(uw, thred, a);
    }

    // Block reduction
#pragma unroll
    for (int off = 16; off > 0; off >>= 1)
        lsum += __shfl_xor_sync(0xFFFFFFFFu, lsum, off);
    if ((tid & 31) == 0) warp_sums[tid >> 5] = lsum;
    __syncthreads();
    if (tid < (NTHREADS / 32)) {
        float v = warp_sums[tid];
#pragma unroll
        for (int off = (NTHREADS / 64); off > 0; off >>= 1)
            v += __shfl_xor_sync(0xFFFFFFFFu, v, off);
        if (tid == 0) g_partial[row] = v;
    }
}

__global__ __launch_bounds__(512)
void consistency_finish(float* __restrict__ out) {
    __shared__ double wsum[16];
    const int tid = threadIdx.x;
    double s = 0.0;
    for (int i = tid; i < NROWS; i += 512) s += (double)g_partial[i];
#pragma unroll
    for (int off = 16; off > 0; off >>= 1)
        s += __shfl_xor_sync(0xFFFFFFFFu, s, off);
    if ((tid & 31) == 0) wsum[tid >> 5] = s;
    __syncthreads();
    if (tid < 16) {
        double v = wsum[tid];
#pragma unroll
        for (int off = 8; off > 0; off >>= 1)
            v += __shfl_xor_sync(0xFFFFFFFFu, v, off);
        if (tid == 0) out[0] = (float)(v / (double)NELEM);
    }
}

extern "C" void kernel_launch(void* const* d_in, const int* in_sizes, int n_in,
                              void* d_out, int out_size) {
    const float* y_true = (const float*)d_in[0];
    const float* y_pred = (const float*)d_in[1];
    float* out = (float*)d_out;
    consistency_main<<<NROWS, NTHREADS>>>(y_true, y_pred);
    consistency_finish<<<1, 512>>>(out);
}

// round 3
// speedup vs baseline: 1.4065x; 1.4065x over previous
#include <cuda_runtime.h>

#define Hh 1024
#define Ww 1024
#define Bb 16
#define DIL 2
#define NTHREADS 256
#define RPB 8                              // rows computed per block
#define NLOAD (RPB + 2 * DIL)              // 12 smem rows per block
#define STRIDE (Ww + 2 * DIL)              // 1028 floats; 4112B = 16B multiple
#define BLKS_PER_IMG (Hh / RPB)            // 128
#define NBLOCKS (Bb * BLKS_PER_IMG)        // 2048
#define NELEM ((long long)Bb * Hh * Ww)
#define SMEM_BYTES (NLOAD * STRIDE * sizeof(float))

__device__ float g_partial[NBLOCKS];

__device__ __forceinline__ void load_win(float* w, const float* base) {
    *reinterpret_cast<float4*>(&w[0]) = *reinterpret_cast<const float4*>(base);
    *reinterpret_cast<float4*>(&w[4]) = *reinterpret_cast<const float4*>(base + 4);
}

__global__ __launch_bounds__(NTHREADS)
void consistency_main(const float* __restrict__ yt, const float* __restrict__ yp) {
    extern __shared__ float sm[];          // NLOAD rows x STRIDE floats
    __shared__ float warp_sums[NTHREADS / 32];

    const int blk = blockIdx.x;            // 0..2047
    const int b   = blk >> 7;              // image index
    const int yg  = (blk & (BLKS_PER_IMG - 1)) * RPB;  // first computed row
    const int tid = threadIdx.x;
    const int x4  = tid * 4;

    const float* img  = yp + (size_t)b * Hh * Ww;
    const float* timg = yt + (size_t)b * Hh * Ww;

    // Fill tile: global rows yg-2 .. yg+9, zero-padded outside image.
    // Front-batched for MLP; stores are 8B-aligned -> two float2 each.
#pragma unroll
    for (int i = 0; i < NLOAD; ++i) {
        const int gy = yg - DIL + i;
        float4 v = make_float4(0.f, 0.f, 0.f, 0.f);
        if (gy >= 0 && gy < Hh)
            v = *reinterpret_cast<const float4*>(img + (size_t)gy * Ww + x4);
        float* row = sm + i * STRIDE;
        *reinterpret_cast<float2*>(row + DIL + x4)     = make_float2(v.x, v.y);
        *reinterpret_cast<float2*>(row + DIL + x4 + 2) = make_float2(v.z, v.w);
    }
    // Zero left/right halos (image boundary zero-pad)
    if (tid < 2 * NLOAD) {
        const int i = tid >> 1;
        float* row = sm + i * STRIDE;
        if (tid & 1) { row[Ww + DIL] = 0.f; row[Ww + DIL + 1] = 0.f; }
        else         { row[0] = 0.f;        row[1] = 0.f; }
    }
    __syncthreads();

    float lsum = 0.f;

    // Two parity chains with rolling windows: each smem window is read once.
#pragma unroll
    for (int c = 0; c < 2; ++c) {
        float w0[8], w1[8], w2[8];
        load_win(w0, sm + (c + 0) * STRIDE + x4);   // row yg+c-2
        load_win(w1, sm + (c + 2) * STRIDE + x4);   // row yg+c
#pragma unroll
        for (int j = c; j < RPB; j += 2) {
            load_win(w2, sm + (j + 4) * STRIDE + x4);  // row yg+j+2
            const float4 t4 = *reinterpret_cast<const float4*>(
                timg + (size_t)(yg + j) * Ww + x4);
            const float tval[4] = { t4.x, t4.y, t4.z, t4.w };
#pragma unroll
            for (int k = 0; k < 4; ++k) {
                const float p = w1[k + 2];
                const float t = tval[k];

                float lp = fmaxf(__logf(p),        -100.0f);
                float l1 = fmaxf(__logf(1.0f - p), -100.0f);
                float a  = -(t * lp + (1.0f - t) * l1);

                float uw;
                uw =           fabsf(p - w0[k]);
                uw = fmaxf(uw, fabsf(p - w0[k + 2]));
                uw = fmaxf(uw, fabsf(p - w0[k + 4]));
                uw = fmaxf(uw, fabsf(p - w1[k]));
                uw = fmaxf(uw, fabsf(p - w1[k + 4]));
                uw = fmaxf(uw, fabsf(p - w2[k]));
                uw = fmaxf(uw, fabsf(p - w2[k + 2]));
                uw = fmaxf(uw, fabsf(p - w2[k + 4]));

                const float thred = (p >= 0.5f) ? p : 0.0f;
                lsum += fmaf(uw, thred, a);
            }
#pragma unroll
            for (int q = 0; q < 8; ++q) { w0[q] = w1[q]; w1[q] = w2[q]; }
        }
    }

    // Block reduction
#pragma unroll
    for (int off = 16; off > 0; off >>= 1)
        lsum += __shfl_xor_sync(0xFFFFFFFFu, lsum, off);
    if ((tid & 31) == 0) warp_sums[tid >> 5] = lsum;
    __syncthreads();
    if (tid < (NTHREADS / 32)) {
        float v = warp_sums[tid];
#pragma unroll
        for (int off = (NTHREADS / 64); off > 0; off >>= 1)
            v += __shfl_xor_sync(0xFFFFFFFFu, v, off);
        if (tid == 0) g_partial[blk] = v;
    }
}

__global__ __launch_bounds__(512)
void consistency_finish(float* __restrict__ out) {
    __shared__ double wsum[16];
    const int tid = threadIdx.x;
    // 2048 partials = 512 threads x one float4
    const float4 v4 = *reinterpret_cast<const float4*>(&g_partial[tid * 4]);
    double s = (double)v4.x + (double)v4.y + (double)v4.z + (double)v4.w;
#pragma unroll
    for (int off = 16; off > 0; off >>= 1)
        s += __shfl_xor_sync(0xFFFFFFFFu, s, off);
    if ((tid & 31) == 0) wsum[tid >> 5] = s;
    __syncthreads();
    if (tid < 16) {
        double v = wsum[tid];
#pragma unroll
        for (int off = 8; off > 0; off >>= 1)
            v += __shfl_xor_sync(0xFFFFFFFFu, v, off);
        if (tid == 0) out[0] = (float)(v / (double)NELEM);
    }
}

extern "C" void kernel_launch(void* const* d_in, const int* in_sizes, int n_in,
                              void* d_out, int out_size) {
    const float* y_true = (const float*)d_in[0];
    const float* y_pred = (const float*)d_in[1];
    float* out = (float*)d_out;
    cudaFuncSetAttribute(consistency_main,
                         cudaFuncAttributeMaxDynamicSharedMemorySize, SMEM_BYTES);
    consistency_main<<<NBLOCKS, NTHREADS, SMEM_BYTES>>>(y_true, y_pred);
    consistency_finish<<<1, 512>>>(out);
}

// round 4
// speedup vs baseline: 1.4087x; 1.0016x over previous
#include <cuda_runtime.h>

#define Hh 1024
#define Ww 1024
#define Bb 16
#define DIL 2
#define NTHREADS 256
#define RPB 16                             // rows computed per block
#define NLOAD (RPB + 2 * DIL)              // 20 smem rows per block
#define STRIDE (Ww + 2 * DIL)              // 1028 floats
#define BLKS_PER_IMG (Hh / RPB)            // 64
#define NBLOCKS (Bb * BLKS_PER_IMG)        // 1024
#define NELEM ((long long)Bb * Hh * Ww)
#define SMEM_BYTES (NLOAD * STRIDE * sizeof(float))

__device__ double       g_sum   = 0.0;
__device__ unsigned int g_count = 0u;

__device__ __forceinline__ void load_win(float* w, const float* base) {
    *reinterpret_cast<float4*>(&w[0]) = *reinterpret_cast<const float4*>(base);
    *reinterpret_cast<float4*>(&w[4]) = *reinterpret_cast<const float4*>(base + 4);
}

__global__ __launch_bounds__(NTHREADS, 2)
void consistency_main(const float* __restrict__ yt, const float* __restrict__ yp,
                      float* __restrict__ out) {
    extern __shared__ float sm[];          // NLOAD rows x STRIDE floats
    __shared__ float warp_sums[NTHREADS / 32];

    const int blk = blockIdx.x;            // 0..1023
    const int b   = blk / BLKS_PER_IMG;
    const int yg  = (blk % BLKS_PER_IMG) * RPB;
    const int tid = threadIdx.x;
    const int x4  = tid * 4;

    const float* img  = yp + (size_t)b * Hh * Ww;
    const float* timg = yt + (size_t)b * Hh * Ww;

    // Fill tile: global rows yg-2 .. yg+RPB+1, zero-padded outside image.
#pragma unroll
    for (int i = 0; i < NLOAD; ++i) {
        const int gy = yg - DIL + i;
        float4 v = make_float4(0.f, 0.f, 0.f, 0.f);
        if (gy >= 0 && gy < Hh)
            v = *reinterpret_cast<const float4*>(img + (size_t)gy * Ww + x4);
        float* row = sm + i * STRIDE;
        *reinterpret_cast<float2*>(row + DIL + x4)     = make_float2(v.x, v.y);
        *reinterpret_cast<float2*>(row + DIL + x4 + 2) = make_float2(v.z, v.w);
    }
    // Zero left/right halos (image boundary zero-pad)
    if (tid < 2 * NLOAD) {
        const int i = tid >> 1;
        float* row = sm + i * STRIDE;
        if (tid & 1) { row[Ww + DIL] = 0.f; row[Ww + DIL + 1] = 0.f; }
        else         { row[0] = 0.f;        row[1] = 0.f; }
    }
    __syncthreads();

    float lsum = 0.f;

    // Two parity chains with rolling windows: each smem window is read once.
#pragma unroll
    for (int c = 0; c < 2; ++c) {
        float w0[8], w1[8], w2[8];
        load_win(w0, sm + (c + 0) * STRIDE + x4);   // row yg+c-2
        load_win(w1, sm + (c + 2) * STRIDE + x4);   // row yg+c
#pragma unroll
        for (int j = c; j < RPB; j += 2) {
            load_win(w2, sm + (j + 4) * STRIDE + x4);  // row yg+j+2
            const float4 t4 = *reinterpret_cast<const float4*>(
                timg + (size_t)(yg + j) * Ww + x4);
            const float tval[4] = { t4.x, t4.y, t4.z, t4.w };
#pragma unroll
            for (int k = 0; k < 4; ++k) {
                const float p = w1[k + 2];
                const float t = tval[k];

                float lp = fmaxf(__logf(p),        -100.0f);
                float l1 = fmaxf(__logf(1.0f - p), -100.0f);
                float a  = -(t * lp + (1.0f - t) * l1);

                float uw;
                uw =           fabsf(p - w0[k]);
                uw = fmaxf(uw, fabsf(p - w0[k + 2]));
                uw = fmaxf(uw, fabsf(p - w0[k + 4]));
                uw = fmaxf(uw, fabsf(p - w1[k]));
                uw = fmaxf(uw, fabsf(p - w1[k + 4]));
                uw = fmaxf(uw, fabsf(p - w2[k]));
                uw = fmaxf(uw, fabsf(p - w2[k + 2]));
                uw = fmaxf(uw, fabsf(p - w2[k + 4]));

                const float thred = (p >= 0.5f) ? p : 0.0f;
                lsum += fmaf(uw, thred, a);
            }
#pragma unroll
            for (int q = 0; q < 8; ++q) { w0[q] = w1[q]; w1[q] = w2[q]; }
        }
    }

    // Block reduction
#pragma unroll
    for (int off = 16; off > 0; off >>= 1)
        lsum += __shfl_xor_sync(0xFFFFFFFFu, lsum, off);
    if ((tid & 31) == 0) warp_sums[tid >> 5] = lsum;
    __syncthreads();
    if (tid == 0) {
        float v = 0.f;
#pragma unroll
        for (int w = 0; w < NTHREADS / 32; ++w) v += warp_sums[w];

        // Fused final reduction: last-arriving block writes the mean.
        atomicAdd(&g_sum, (double)v);
        __threadfence();
        const unsigned int old = atomicAdd(&g_count, 1u);
        if (old == NBLOCKS - 1) {
            const double total = atomicAdd(&g_sum, 0.0);   // L2-coherent read
            out[0] = (float)(total / (double)NELEM);
            g_sum   = 0.0;                                  // reset for next graph replay
            __threadfence();
            g_count = 0u;
        }
    }
}

extern "C" void kernel_launch(void* const* d_in, const int* in_sizes, int n_in,
                              void* d_out, int out_size) {
    const float* y_true = (const float*)d_in[0];
    const float* y_pred = (const float*)d_in[1];
    float* out = (float*)d_out;
    cudaFuncSetAttribute(consistency_main,
                         cudaFuncAttributeMaxDynamicSharedMemorySize, SMEM_BYTES);
    consistency_main<<<NBLOCKS, NTHREADS, SMEM_BYTES>>>(y_true, y_pred, out);
}